// round 7
// baseline (speedup 1.0000x reference)
#include <cuda_runtime.h>
#include <cuda_bf16.h>
#include <float.h>
#include <math.h>
#include <stdint.h>

#define NN 8192
#define DD 128
#define CC 7
#define KNN 5
#define EPSF 1e-6f

#define BM 128
#define BN 128
#define THREADS 512
#define NT 64                          // 8192/128 blocks per side
#define SLOTS 68                       // 64 col-side + 4 row-side

#define ASTRIDE 272                    // 128 bf16 = 256B + 16B pad
#define CSTRIDE 132                    // floats

// ---------------- smem map (bytes) ----------------
#define SM_TG   0                       // int  [2][128]
#define SM_CN   1024                    // float[2][128]
#define SM_RN   2048                    // float[2][128]
#define SM_CNA  3072                    // float[128]
#define SM_TGA  3584                    // int[128]
#define SM_A    4096                    // 34816
#define SM_B    38912                   // 2 * 34816
#define SM_BSTG 34816
#define SM_C    108544                  // 128*132*4 = 67584 (also flush overlay 40960)
#define SM_P    176128                  // 128*4*5*4 = 10240
#define SM_TOTAL 186368

// ---------------- device scratch ----------------
__device__ __nv_bfloat16 g_hi[NN * DD];
__device__ float  g_rn[NN];
__device__ float  g_cn[NN];
__device__ __align__(16) float g_p5[NN][SLOTS][KNN];
__device__ double g_accCE;
__device__ double g_accPair;

// ---------------- PTX helpers ----------------
__device__ __forceinline__ uint32_t smem_u32(const void* p) {
    uint32_t a;
    asm("{ .reg .u64 t; cvta.to.shared.u64 t, %1; cvt.u32.u64 %0, t; }" : "=r"(a) : "l"(p));
    return a;
}
__device__ __forceinline__ void cp16(uint32_t s, const void* g) {
    asm volatile("cp.async.cg.shared.global [%0], [%1], 16;" :: "r"(s), "l"(g));
}
#define CP_COMMIT() asm volatile("cp.async.commit_group;" ::: "memory")
#define CP_WAIT1()  asm volatile("cp.async.wait_group 1;" ::: "memory")
#define CP_WAIT0()  asm volatile("cp.async.wait_group 0;" ::: "memory")

__device__ __forceinline__ void ldsm4(uint32_t* r, uint32_t a) {
    asm volatile("ldmatrix.sync.aligned.m8n8.x4.shared.b16 {%0,%1,%2,%3}, [%4];"
                 : "=r"(r[0]), "=r"(r[1]), "=r"(r[2]), "=r"(r[3]) : "r"(a));
}
__device__ __forceinline__ void ldsm2(uint32_t* r, uint32_t a) {
    asm volatile("ldmatrix.sync.aligned.m8n8.x2.shared.b16 {%0,%1}, [%2];"
                 : "=r"(r[0]), "=r"(r[1]) : "r"(a));
}
__device__ __forceinline__ void mma_bf16(float* c, const uint32_t* a, const uint32_t* b) {
    asm volatile("mma.sync.aligned.m16n8k16.row.col.f32.bf16.bf16.f32 "
                 "{%0,%1,%2,%3}, {%4,%5,%6,%7}, {%8,%9}, {%0,%1,%2,%3};"
                 : "+f"(c[0]), "+f"(c[1]), "+f"(c[2]), "+f"(c[3])
                 : "r"(a[0]), "r"(a[1]), "r"(a[2]), "r"(a[3]), "r"(b[0]), "r"(b[1]));
}

// top-5 insert (min-5, th = current max)
#define T5_INSERT(arr, thv, val)                                              \
    do {                                                                      \
        int _mi = 0; float _mv = (arr)[0];                                    \
        _Pragma("unroll")                                                     \
        for (int _k = 1; _k < KNN; _k++)                                      \
            if ((arr)[_k] > _mv) { _mv = (arr)[_k]; _mi = _k; }               \
        _Pragma("unroll")                                                     \
        for (int _k = 0; _k < KNN; _k++) if (_k == _mi) (arr)[_k] = (val);    \
        (thv) = (arr)[0];                                                     \
        _Pragma("unroll")                                                     \
        for (int _k = 1; _k < KNN; _k++) (thv) = fmaxf((thv), (arr)[_k]);     \
    } while (0)

// ---------------- small kernels ----------------
__global__ void k_init() { g_accCE = 0.0; g_accPair = 0.0; }

__global__ void k_initP() {
    int idx = blockIdx.x * blockDim.x + threadIdx.x;   // NN*SLOTS*KNN/4 threads
    float4 v = {FLT_MAX, FLT_MAX, FLT_MAX, FLT_MAX};
    reinterpret_cast<float4*>(g_p5)[idx] = v;
}

__global__ void k_convert(const float* __restrict__ x) {
    int idx = blockIdx.x * blockDim.x + threadIdx.x;
    float4 v = reinterpret_cast<const float4*>(x)[idx];
    __nv_bfloat162 hh0 = {__float2bfloat16(v.x), __float2bfloat16(v.y)};
    __nv_bfloat162 hh1 = {__float2bfloat16(v.z), __float2bfloat16(v.w)};
    reinterpret_cast<__nv_bfloat162*>(g_hi)[idx * 2]     = hh0;
    reinterpret_cast<__nv_bfloat162*>(g_hi)[idx * 2 + 1] = hh1;
}

__global__ void k_norms(const float* __restrict__ x) {
    int row  = blockIdx.x * 8 + (threadIdx.x >> 5);
    int lane = threadIdx.x & 31;
    float4 v = reinterpret_cast<const float4*>(x + (size_t)row * DD)[lane];
    float s  = v.x + v.y + v.z + v.w;
    float n2 = v.x * v.x + v.y * v.y + v.z * v.z + v.w * v.w;
#pragma unroll
    for (int o = 16; o > 0; o >>= 1) {
        s  += __shfl_xor_sync(0xffffffffu, s, o);
        n2 += __shfl_xor_sync(0xffffffffu, n2, o);
    }
    if (lane == 0) {
        g_rn[row] = n2 + 2.0f * EPSF * s + (float)DD * EPSF * EPSF;
        g_cn[row] = n2 - 2.0f * EPSF * s;
    }
}

__global__ void k_ce(const float* __restrict__ sc, const int* __restrict__ tg) {
    int i = blockIdx.x * blockDim.x + threadIdx.x;
    const float* s = sc + (size_t)i * CC;
    float m = s[0];
#pragma unroll
    for (int c = 1; c < CC; c++) m = fmaxf(m, s[c]);
    float sum = 0.f;
#pragma unroll
    for (int c = 0; c < CC; c++) sum += expf(s[c] - m);
    float ce = m + logf(sum) - s[tg[i]];

    __shared__ double sh[128];
    sh[threadIdx.x] = (double)ce;
    __syncthreads();
#pragma unroll
    for (int o = 64; o > 0; o >>= 1) {
        if (threadIdx.x < o) sh[threadIdx.x] += sh[threadIdx.x + o];
        __syncthreads();
    }
    if (threadIdx.x == 0) atomicAdd(&g_accCE, sh[0]);
}

// ---------------- triangular fused GEMM + dual top-5 ----------------
__global__ void __launch_bounds__(THREADS, 1)
k_dist(const int* __restrict__ tgt) {
    extern __shared__ char smem[];
    uint32_t smb = smem_u32(smem);
    int tid  = threadIdx.x;
    int lane = tid & 31;
    int w    = tid >> 5;
    int wm   = w >> 2;
    int wn   = w & 3;

    int p  = blockIdx.x >> 2;       // strip pair 0..31
    int sI = blockIdx.x & 3;        // chunk within pair
    int a1 = p, a2 = 63 - p;
    int n1 = NT - a1;
    int tBeg = (sI == 0) ? 0 : 17 + 16 * (sI - 1);
    int tEnd = tBeg + ((sI == 0) ? 17 : 16);

    int*   sTG = (int*)(smem + SM_TG);
    float* sCN = (float*)(smem + SM_CN);
    float* sRN = (float*)(smem + SM_RN);
    float* cnA = (float*)(smem + SM_CNA);
    int*   tgA = (int*)(smem + SM_TGA);
    float* Cs  = (float*)(smem + SM_C);
    float* Pb  = (float*)(smem + SM_P);

    int lrow[4];
#pragma unroll
    for (int q = 0; q < 4; q++)
        lrow[q] = wm * 32 + (lane >> 2) + ((q & 1) << 3) + ((q >> 1) << 4);

    float rnq[4]; int tgq[4];
    float t5[4][KNN]; float th[4];

    uint32_t aOff = smb + SM_A + (wm * 32 + (lane & 15)) * ASTRIDE + (lane >> 4) * 16;
    uint32_t bRow = (wn * 32 + (lane & 7)) * ASTRIDE + ((lane >> 3) & 1) * 16;

    // ---- prologue: issue B(tBeg) (uncommitted) + slot fill ----
    {
        int b0 = (tBeg < n1) ? a1 + tBeg : a2 + (tBeg - n1);
        int jb = b0 * BN;
        uint32_t bs = smb + SM_B + (tBeg & 1) * SM_BSTG;
#pragma unroll
        for (int itc = 0; itc < 4; itc++) {
            int q   = itc * THREADS + tid;
            int row = q >> 4;
            int c   = q & 15;
            cp16(bs + row * ASTRIDE + c * 16,
                 g_hi + (size_t)(jb + row) * DD + c * 8);
        }
        if (tid < BN) {
            int sl = (tBeg & 1) * BN;
            sTG[sl + tid] = tgt[jb + tid];
            sCN[sl + tid] = g_cn[jb + tid];
            sRN[sl + tid] = g_rn[jb + tid];
        }
    }

    int curA = -1;

    for (int t = tBeg; t < tEnd; t++) {
        int a = (t < n1) ? a1 : a2;
        int b = (t < n1) ? a1 + t : a2 + (t - n1);
        int rowBase = a * BM;
        int jb      = b * BN;

        __syncthreads();            // prior tile epilogues complete

        bool reload = (a != curA);
        if (reload) {
            if (curA >= 0) {
                // ---- flush row-side partials for old A block ----
                float* M = Cs;                       // overlay (free now)
                int slot16 = wn * 4 + (lane & 3);
#pragma unroll
                for (int q = 0; q < 4; q++)
#pragma unroll
                    for (int k = 0; k < KNN; k++)
                        M[(lrow[q] * 16 + slot16) * KNN + k] = t5[q][k];
                __syncthreads();
                if (tid < BM) {
                    const float* mrow = M + tid * 16 * KNN;
                    float best[KNN], bth = FLT_MAX;
#pragma unroll
                    for (int k = 0; k < KNN; k++) best[k] = FLT_MAX;
                    for (int j = 0; j < 16 * KNN; j++) {
                        float v = mrow[j];
                        if (v < bth) T5_INSERT(best, bth, v);
                    }
#pragma unroll
                    for (int k = 0; k < KNN; k++)
                        g_p5[curA * BM + tid][64 + sI][k] = best[k];
                }
                __syncthreads();
            }
            // issue A loads
#pragma unroll
            for (int itc = 0; itc < 4; itc++) {
                int q   = itc * THREADS + tid;
                int row = q >> 4;
                int c   = q & 15;
                cp16(smb + SM_A + row * ASTRIDE + c * 16,
                     g_hi + (size_t)(rowBase + row) * DD + c * 8);
            }
            if (tid < BM) {
                cnA[tid] = g_cn[rowBase + tid];
                tgA[tid] = tgt[rowBase + tid];
            }
            // reinit per-thread row state
#pragma unroll
            for (int q = 0; q < 4; q++) {
                rnq[q] = g_rn[rowBase + lrow[q]];
                tgq[q] = tgt[rowBase + lrow[q]];
                th[q]  = FLT_MAX;
#pragma unroll
                for (int k = 0; k < KNN; k++) t5[q][k] = FLT_MAX;
            }
            curA = a;
        }

        // prefetch B(t+1) + slots
        if (t + 1 < tEnd) {
            int bN = (t + 1 < n1) ? a1 + (t + 1) : a2 + ((t + 1) - n1);
            int jbN = bN * BN;
            uint32_t bs = smb + SM_B + ((t + 1) & 1) * SM_BSTG;
#pragma unroll
            for (int itc = 0; itc < 4; itc++) {
                int q   = itc * THREADS + tid;
                int row = q >> 4;
                int c   = q & 15;
                cp16(bs + row * ASTRIDE + c * 16,
                     g_hi + (size_t)(jbN + row) * DD + c * 8);
            }
            if (tid < BN) {
                int sl = ((t + 1) & 1) * BN;
                sTG[sl + tid] = tgt[jbN + tid];
                sCN[sl + tid] = g_cn[jbN + tid];
                sRN[sl + tid] = g_rn[jbN + tid];
            }
        }
        CP_COMMIT();
        if (reload) CP_WAIT0(); else CP_WAIT1();
        __syncthreads();

        // ---- MMA over K=128 ----
        float acc[2][4][4];
#pragma unroll
        for (int mi = 0; mi < 2; mi++)
#pragma unroll
            for (int ni = 0; ni < 4; ni++)
#pragma unroll
                for (int q = 0; q < 4; q++) acc[mi][ni][q] = 0.f;

        uint32_t bH = smb + SM_B + (t & 1) * SM_BSTG + bRow;

#pragma unroll
        for (int kk = 0; kk < 8; kk++) {
            uint32_t ah[2][4], bh[4][2];
#pragma unroll
            for (int mi = 0; mi < 2; mi++)
                ldsm4(ah[mi], aOff + mi * 16 * ASTRIDE + kk * 32);
#pragma unroll
            for (int ni = 0; ni < 4; ni++)
                ldsm2(bh[ni], bH + ni * 8 * ASTRIDE + kk * 32);
#pragma unroll
            for (int mi = 0; mi < 2; mi++)
#pragma unroll
                for (int ni = 0; ni < 4; ni++)
                    mma_bf16(acc[mi][ni], ah[mi], bh[ni]);
        }

        // ---- row-side register epilogue ----
        {
            int slot = (t & 1) * BN;
            int sj[4];
#pragma unroll
            for (int q = 0; q < 4; q++) sj[q] = (rowBase + lrow[q]) - jb;

#pragma unroll
            for (int ni = 0; ni < 4; ni++) {
                int cb = wn * 32 + ni * 8 + 2 * (lane & 3);
                float cn0 = sCN[slot + cb], cn1 = sCN[slot + cb + 1];
                int   tg0 = sTG[slot + cb], tg1 = sTG[slot + cb + 1];
#pragma unroll
                for (int mi = 0; mi < 2; mi++) {
#pragma unroll
                    for (int h = 0; h < 2; h++) {
                        int q = mi * 2 + h;
                        float d2a = fmaf(-2.0f, acc[mi][ni][2 * h],     rnq[q] + cn0);
                        float d2b = fmaf(-2.0f, acc[mi][ni][2 * h + 1], rnq[q] + cn1);
                        if (d2a < th[q] && tg0 == tgq[q] && cb != sj[q])
                            T5_INSERT(t5[q], th[q], d2a);
                        if (d2b < th[q] && tg1 == tgq[q] && (cb + 1) != sj[q])
                            T5_INSERT(t5[q], th[q], d2b);
                    }
                }
            }
        }

        // ---- column-side epilogue (off-diagonal tiles only) ----
        if (a != b) {
            // stage C
#pragma unroll
            for (int mi = 0; mi < 2; mi++) {
                int r0 = wm * 32 + mi * 16 + (lane >> 2);
#pragma unroll
                for (int ni = 0; ni < 4; ni++) {
                    int col = wn * 32 + ni * 8 + 2 * (lane & 3);
                    *reinterpret_cast<float2*>(&Cs[r0 * CSTRIDE + col]) =
                        make_float2(acc[mi][ni][0], acc[mi][ni][1]);
                    *reinterpret_cast<float2*>(&Cs[(r0 + 8) * CSTRIDE + col]) =
                        make_float2(acc[mi][ni][2], acc[mi][ni][3]);
                }
            }
            __syncthreads();

            int col  = tid >> 2;
            int quad = tid & 3;
            int slot = (t & 1) * BN;
            float rnj = sRN[slot + col];
            int   tgj = sTG[slot + col];
            float ct5[KNN], cth = FLT_MAX;
#pragma unroll
            for (int k = 0; k < KNN; k++) ct5[k] = FLT_MAX;
#pragma unroll 4
            for (int jj = 0; jj < 32; jj++) {
                int r = quad + 4 * jj;
                float g = Cs[r * CSTRIDE + col];
                float d2 = fmaf(-2.0f, g, rnj + cnA[r]);
                if (d2 < cth && tgA[r] == tgj)
                    T5_INSERT(ct5, cth, d2);
            }
#pragma unroll
            for (int k = 0; k < KNN; k++)
                Pb[(col * 4 + quad) * KNN + k] = ct5[k];
            __syncthreads();
            if (tid < BN) {
                const float* prow = Pb + tid * 4 * KNN;
                float best[KNN], bth = FLT_MAX;
#pragma unroll
                for (int k = 0; k < KNN; k++) best[k] = FLT_MAX;
#pragma unroll
                for (int j = 0; j < 4 * KNN; j++) {
                    float v = prow[j];
                    if (v < bth) T5_INSERT(best, bth, v);
                }
#pragma unroll
                for (int k = 0; k < KNN; k++)
                    g_p5[jb + tid][a][k] = best[k];
            }
        }
    }

    // ---- final flush of row-side partials ----
    __syncthreads();
    {
        float* M = Cs;
        int slot16 = wn * 4 + (lane & 3);
#pragma unroll
        for (int q = 0; q < 4; q++)
#pragma unroll
            for (int k = 0; k < KNN; k++)
                M[(lrow[q] * 16 + slot16) * KNN + k] = t5[q][k];
        __syncthreads();
        if (tid < BM) {
            const float* mrow = M + tid * 16 * KNN;
            float best[KNN], bth = FLT_MAX;
#pragma unroll
            for (int k = 0; k < KNN; k++) best[k] = FLT_MAX;
            for (int j = 0; j < 16 * KNN; j++) {
                float v = mrow[j];
                if (v < bth) T5_INSERT(best, bth, v);
            }
#pragma unroll
            for (int k = 0; k < KNN; k++)
                g_p5[curA * BM + tid][64 + sI][k] = best[k];
        }
    }
}

// ---------------- merge + pair sum ----------------
__global__ void k_merge() {
    int i = blockIdx.x * blockDim.x + threadIdx.x;
    const float* base = &g_p5[i][0][0];
    float best[KNN], bth = FLT_MAX;
#pragma unroll
    for (int k = 0; k < KNN; k++) best[k] = FLT_MAX;
    for (int j = 0; j < SLOTS * KNN; j++) {
        float v = base[j];
        if (v < bth) T5_INSERT(best, bth, v);
    }
    float sum = 0.f;
#pragma unroll
    for (int k = 0; k < KNN; k++)
        if (best[k] < 1e37f) sum += best[k];

    __shared__ double sh[256];
    sh[threadIdx.x] = (double)sum / (double)DD;
    __syncthreads();
#pragma unroll
    for (int o = 128; o > 0; o >>= 1) {
        if (threadIdx.x < o) sh[threadIdx.x] += sh[threadIdx.x + o];
        __syncthreads();
    }
    if (threadIdx.x == 0) atomicAdd(&g_accPair, sh[0]);
}

__global__ void k_final(float* out) {
    out[0] = (float)(g_accCE / (double)NN + (0.5 / (double)KNN) * g_accPair);
}

// ---------------- launch ----------------
extern "C" void kernel_launch(void* const* d_in, const int* in_sizes, int n_in,
                              void* d_out, int out_size) {
    const float* x  = nullptr;
    const float* sc = nullptr;
    const int*   tg = nullptr;
    for (int i = 0; i < n_in; i++) {
        if (in_sizes[i] == NN * DD)      x  = (const float*)d_in[i];
        else if (in_sizes[i] == NN * CC) sc = (const float*)d_in[i];
        else if (in_sizes[i] == NN)      tg = (const int*)d_in[i];
    }
    float* out = (float*)d_out;

    cudaFuncSetAttribute(k_dist, cudaFuncAttributeMaxDynamicSharedMemorySize, SM_TOTAL);

    k_init<<<1, 1>>>();
    k_initP<<<NN * SLOTS * KNN / 4 / 256, 256>>>();
    k_convert<<<NN * DD / 4 / 256, 256>>>(x);
    k_norms<<<NN / 8, 256>>>(x);
    k_ce<<<NN / 128, 128>>>(sc, tg);
    k_dist<<<128, THREADS, SM_TOTAL>>>(tg);
    k_merge<<<NN / 256, 256>>>();
    k_final<<<1, 1>>>(out);
}

// round 8
// speedup vs baseline: 1.6468x; 1.6468x over previous
#include <cuda_runtime.h>
#include <cuda_bf16.h>
#include <float.h>
#include <math.h>
#include <stdint.h>

#define NN 8192
#define DD 128
#define CC 7
#define KNN 5
#define EPSF 1e-6f

#define BM 128
#define BN 128
#define THREADS 512
#define JHALVES 2
#define JTILES (NN / JHALVES / BN)     // 32 j-tiles per CTA
#define ITILES (NN / BM)               // 64 i-tiles

#define ASTRIDE 272                    // 128 bf16 = 256B + 16B pad

// ---------------- smem map (bytes) ----------------
#define SM_CT   0                       // float2 [2][128]  (cn, tg-bits)
#define SM_A    2048                    // 128 * 272 = 34816
#define SM_B    36864                   // 2 stages * 34816
#define SM_BSTG 34816
#define SM_TOTAL 106496
// final-merge overlay (reuses B region): 128 rows * 16 slots * 5 floats = 40960 B

// ---------------- device scratch ----------------
__device__ __nv_bfloat16 g_hi[NN * DD];
__device__ float  g_rn[NN];
__device__ float  g_cn[NN];
__device__ float  g_part5[JHALVES][NN][KNN];
__device__ double g_accCE;
__device__ double g_accPair;

// ---------------- PTX helpers ----------------
__device__ __forceinline__ uint32_t smem_u32(const void* p) {
    uint32_t a;
    asm("{ .reg .u64 t; cvta.to.shared.u64 t, %1; cvt.u32.u64 %0, t; }" : "=r"(a) : "l"(p));
    return a;
}
__device__ __forceinline__ void cp16(uint32_t s, const void* g) {
    asm volatile("cp.async.cg.shared.global [%0], [%1], 16;" :: "r"(s), "l"(g));
}
#define CP_COMMIT() asm volatile("cp.async.commit_group;" ::: "memory")
#define CP_WAIT1()  asm volatile("cp.async.wait_group 1;" ::: "memory")

__device__ __forceinline__ void ldsm4(uint32_t* r, uint32_t a) {
    asm volatile("ldmatrix.sync.aligned.m8n8.x4.shared.b16 {%0,%1,%2,%3}, [%4];"
                 : "=r"(r[0]), "=r"(r[1]), "=r"(r[2]), "=r"(r[3]) : "r"(a));
}
__device__ __forceinline__ void mma_bf16(float* c, const uint32_t* a, const uint32_t* b) {
    asm volatile("mma.sync.aligned.m16n8k16.row.col.f32.bf16.bf16.f32 "
                 "{%0,%1,%2,%3}, {%4,%5,%6,%7}, {%8,%9}, {%0,%1,%2,%3};"
                 : "+f"(c[0]), "+f"(c[1]), "+f"(c[2]), "+f"(c[3])
                 : "r"(a[0]), "r"(a[1]), "r"(a[2]), "r"(a[3]), "r"(b[0]), "r"(b[1]));
}

#define T5_INSERT(arr, thv, val)                                              \
    do {                                                                      \
        int _mi = 0; float _mv = (arr)[0];                                    \
        _Pragma("unroll")                                                     \
        for (int _k = 1; _k < KNN; _k++)                                      \
            if ((arr)[_k] > _mv) { _mv = (arr)[_k]; _mi = _k; }               \
        _Pragma("unroll")                                                     \
        for (int _k = 0; _k < KNN; _k++) if (_k == _mi) (arr)[_k] = (val);    \
        (thv) = (arr)[0];                                                     \
        _Pragma("unroll")                                                     \
        for (int _k = 1; _k < KNN; _k++) (thv) = fmaxf((thv), (arr)[_k]);     \
    } while (0)

// ---------------- small kernels ----------------
__global__ void k_init() { g_accCE = 0.0; g_accPair = 0.0; }

__global__ void k_convert(const float* __restrict__ x) {
    int idx = blockIdx.x * blockDim.x + threadIdx.x;     // NN*DD/4 threads
    float4 v = reinterpret_cast<const float4*>(x)[idx];
    __nv_bfloat162 hh0 = {__float2bfloat16(v.x), __float2bfloat16(v.y)};
    __nv_bfloat162 hh1 = {__float2bfloat16(v.z), __float2bfloat16(v.w)};
    reinterpret_cast<__nv_bfloat162*>(g_hi)[idx * 2]     = hh0;
    reinterpret_cast<__nv_bfloat162*>(g_hi)[idx * 2 + 1] = hh1;
}

__global__ void k_norms(const float* __restrict__ x) {
    int row  = blockIdx.x * 8 + (threadIdx.x >> 5);
    int lane = threadIdx.x & 31;
    float4 v = reinterpret_cast<const float4*>(x + (size_t)row * DD)[lane];
    float s  = v.x + v.y + v.z + v.w;
    float n2 = v.x * v.x + v.y * v.y + v.z * v.z + v.w * v.w;
#pragma unroll
    for (int o = 16; o > 0; o >>= 1) {
        s  += __shfl_xor_sync(0xffffffffu, s, o);
        n2 += __shfl_xor_sync(0xffffffffu, n2, o);
    }
    if (lane == 0) {
        g_rn[row] = n2 + 2.0f * EPSF * s + (float)DD * EPSF * EPSF;
        g_cn[row] = n2 - 2.0f * EPSF * s;
    }
}

__global__ void k_ce(const float* __restrict__ sc, const int* __restrict__ tg) {
    int i = blockIdx.x * blockDim.x + threadIdx.x;
    const float* s = sc + (size_t)i * CC;
    float m = s[0];
#pragma unroll
    for (int c = 1; c < CC; c++) m = fmaxf(m, s[c]);
    float sum = 0.f;
#pragma unroll
    for (int c = 0; c < CC; c++) sum += expf(s[c] - m);
    float ce = m + logf(sum) - s[tg[i]];

    __shared__ double sh[128];
    sh[threadIdx.x] = (double)ce;
    __syncthreads();
#pragma unroll
    for (int o = 64; o > 0; o >>= 1) {
        if (threadIdx.x < o) sh[threadIdx.x] += sh[threadIdx.x + o];
        __syncthreads();
    }
    if (threadIdx.x == 0) atomicAdd(&g_accCE, sh[0]);
}

// ---------------- fused bf16 mma.sync GEMM + register top-5 ----------------
__global__ void __launch_bounds__(THREADS, 1)
k_dist(const int* __restrict__ tgt) {
    extern __shared__ char smem[];
    uint32_t smb = smem_u32(smem);
    int tid  = threadIdx.x;
    int lane = tid & 31;
    int w    = tid >> 5;
    int wm   = w >> 2;          // 0..3 : 32-row block
    int wn   = w & 3;           // 0..3 : 32-col block

    int it      = blockIdx.x >> 1;
    int jhalf   = blockIdx.x & 1;
    int rowBase = it * BM;
    int jBase0  = jhalf * (NN / JHALVES);

    float2* sCT = (float2*)(smem + SM_CT);   // [2][128] : {cn, tg-bits}

    // ---- prologue: A (2048 chunks) ----
#pragma unroll
    for (int itc = 0; itc < 4; itc++) {
        int q   = itc * THREADS + tid;
        int row = q >> 4;
        int c   = q & 15;
        cp16(smb + SM_A + row * ASTRIDE + c * 16,
             g_hi + (size_t)(rowBase + row) * DD + c * 8);
    }
    // ---- B tile 0 (2048 chunks) ----
#pragma unroll
    for (int itc = 0; itc < 4; itc++) {
        int q   = itc * THREADS + tid;
        int row = q >> 4;
        int c   = q & 15;
        cp16(smb + SM_B + row * ASTRIDE + c * 16,
             g_hi + (size_t)(jBase0 + row) * DD + c * 8);
    }
    CP_COMMIT();
    if (tid < BN)
        sCT[tid] = make_float2(g_cn[jBase0 + tid], __int_as_float(tgt[jBase0 + tid]));

    // ---- per-thread row state ----
    int   lrow[4];
    float rnq[4];
    int   tgq[4];
#pragma unroll
    for (int q = 0; q < 4; q++) {
        lrow[q] = wm * 32 + (lane >> 2) + ((q & 1) << 3) + ((q >> 1) << 4);
        rnq[q]  = g_rn[rowBase + lrow[q]];
        tgq[q]  = tgt[rowBase + lrow[q]];
    }
    float t5[4][KNN];
    float th[4];
#pragma unroll
    for (int q = 0; q < 4; q++) {
        th[q] = FLT_MAX;
#pragma unroll
        for (int k = 0; k < KNN; k++) t5[q][k] = FLT_MAX;
    }

    // ldmatrix base addresses
    uint32_t aOff  = smb + SM_A + (wm * 32 + (lane & 15)) * ASTRIDE + (lane >> 4) * 16;
    // B x4: groups 0..3 -> (n-block lo k-half0, lo k-half1, hi k-half0, hi k-half1)
    uint32_t bRow4 = (wn * 32 + ((lane >> 4) << 3) + (lane & 7)) * ASTRIDE + (((lane >> 3) & 1) << 4);

    for (int u = 0; u < JTILES; u++) {
        __syncthreads();              // epilogue(u-1) done: safe to overwrite stage
        if (u + 1 < JTILES) {
            int jb = jBase0 + (u + 1) * BN;
            uint32_t bs = smb + SM_B + ((u + 1) & 1) * SM_BSTG;
#pragma unroll
            for (int itc = 0; itc < 4; itc++) {
                int q   = itc * THREADS + tid;
                int row = q >> 4;
                int c   = q & 15;
                cp16(bs + row * ASTRIDE + c * 16,
                     g_hi + (size_t)(jb + row) * DD + c * 8);
            }
            if (tid < BN) {
                int slot = (u + 1) & 1;
                sCT[slot * BN + tid] =
                    make_float2(g_cn[jb + tid], __int_as_float(tgt[jb + tid]));
            }
        }
        CP_COMMIT();
        CP_WAIT1();                   // B(u) (and A) resident
        __syncthreads();

        // ---- preload this tile's cn/tg columns into registers (4x LDS.128) ----
        float4 ct[4];
        {
            int slot = (u & 1) * BN;
#pragma unroll
            for (int ni = 0; ni < 4; ni++) {
                int cb = wn * 32 + ni * 8 + 2 * (lane & 3);
                ct[ni] = *reinterpret_cast<const float4*>(&sCT[slot + cb]);
            }
        }

        // ---- MMA: acc = A*B^T over K=128 ----
        float acc[2][4][4];
#pragma unroll
        for (int mi = 0; mi < 2; mi++)
#pragma unroll
            for (int ni = 0; ni < 4; ni++)
#pragma unroll
                for (int q = 0; q < 4; q++) acc[mi][ni][q] = 0.f;

        uint32_t bH = smb + SM_B + (u & 1) * SM_BSTG + bRow4;

#pragma unroll
        for (int kk = 0; kk < 8; kk++) {
            uint32_t ah[2][4], bh[4][2];
#pragma unroll
            for (int mi = 0; mi < 2; mi++)
                ldsm4(ah[mi], aOff + mi * 16 * ASTRIDE + kk * 32);
#pragma unroll
            for (int pr = 0; pr < 2; pr++)
                ldsm4(&bh[pr * 2][0], bH + pr * 16 * ASTRIDE + kk * 32);
#pragma unroll
            for (int mi = 0; mi < 2; mi++)
#pragma unroll
                for (int ni = 0; ni < 4; ni++)
                    mma_bf16(acc[mi][ni], ah[mi], bh[ni]);
        }

        // ---- register epilogue: d2 + top-5 directly on acc ----
        {
            int jb = jBase0 + u * BN;
            int sj[4];
#pragma unroll
            for (int q = 0; q < 4; q++) sj[q] = (rowBase + lrow[q]) - jb;

#pragma unroll
            for (int ni = 0; ni < 4; ni++) {
                int cb = wn * 32 + ni * 8 + 2 * (lane & 3);
                float cn0 = ct[ni].x, cn1 = ct[ni].z;
                int   tg0 = __float_as_int(ct[ni].y), tg1 = __float_as_int(ct[ni].w);
#pragma unroll
                for (int mi = 0; mi < 2; mi++) {
#pragma unroll
                    for (int h = 0; h < 2; h++) {
                        int q = mi * 2 + h;
                        float d2a = fmaf(-2.0f, acc[mi][ni][2 * h],     rnq[q] + cn0);
                        float d2b = fmaf(-2.0f, acc[mi][ni][2 * h + 1], rnq[q] + cn1);
                        if (d2a < th[q] && tg0 == tgq[q] && cb != sj[q])
                            T5_INSERT(t5[q], th[q], d2a);
                        if (d2b < th[q] && tg1 == tgq[q] && (cb + 1) != sj[q])
                            T5_INSERT(t5[q], th[q], d2b);
                    }
                }
            }
        }
    }

    // ---- in-CTA merge: 16 threads per row -> 5 smallest of 80 ----
    __syncthreads();
    float* M = (float*)(smem + SM_B);      // overlay, 40960 B
    int slot16 = wn * 4 + (lane & 3);
#pragma unroll
    for (int q = 0; q < 4; q++)
#pragma unroll
        for (int k = 0; k < KNN; k++)
            M[(lrow[q] * 16 + slot16) * KNN + k] = t5[q][k];
    __syncthreads();

    if (tid < BM) {
        const float* mrow = M + tid * 16 * KNN;
        float best[KNN], bth = FLT_MAX;
#pragma unroll
        for (int k = 0; k < KNN; k++) best[k] = FLT_MAX;
        for (int j = 0; j < 16 * KNN; j++) {
            float v = mrow[j];
            if (v < bth) T5_INSERT(best, bth, v);
        }
#pragma unroll
        for (int k = 0; k < KNN; k++) g_part5[jhalf][rowBase + tid][k] = best[k];
    }
}

// ---------------- merge + pair sum ----------------
__global__ void k_merge() {
    int i = blockIdx.x * blockDim.x + threadIdx.x;
    float v[JHALVES * KNN];
#pragma unroll
    for (int sp = 0; sp < JHALVES; sp++)
#pragma unroll
        for (int k = 0; k < KNN; k++) v[sp * KNN + k] = g_part5[sp][i][k];

    float sum = 0.f;
#pragma unroll
    for (int sel = 0; sel < KNN; sel++) {
        float mv = v[0]; int mi = 0;
#pragma unroll
        for (int k = 1; k < JHALVES * KNN; k++)
            if (v[k] < mv) { mv = v[k]; mi = k; }
        if (mv < 1e37f) sum += mv;
#pragma unroll
        for (int k = 0; k < JHALVES * KNN; k++)
            if (k == mi) v[k] = FLT_MAX;
    }

    __shared__ double sh[256];
    sh[threadIdx.x] = (double)sum / (double)DD;
    __syncthreads();
#pragma unroll
    for (int o = 128; o > 0; o >>= 1) {
        if (threadIdx.x < o) sh[threadIdx.x] += sh[threadIdx.x + o];
        __syncthreads();
    }
    if (threadIdx.x == 0) atomicAdd(&g_accPair, sh[0]);
}

__global__ void k_final(float* out) {
    out[0] = (float)(g_accCE / (double)NN + (0.5 / (double)KNN) * g_accPair);
}

// ---------------- launch ----------------
extern "C" void kernel_launch(void* const* d_in, const int* in_sizes, int n_in,
                              void* d_out, int out_size) {
    const float* x  = nullptr;
    const float* sc = nullptr;
    const int*   tg = nullptr;
    for (int i = 0; i < n_in; i++) {
        if (in_sizes[i] == NN * DD)      x  = (const float*)d_in[i];
        else if (in_sizes[i] == NN * CC) sc = (const float*)d_in[i];
        else if (in_sizes[i] == NN)      tg = (const int*)d_in[i];
    }
    float* out = (float*)d_out;

    cudaFuncSetAttribute(k_dist, cudaFuncAttributeMaxDynamicSharedMemorySize, SM_TOTAL);

    k_init<<<1, 1>>>();
    k_convert<<<NN * DD / 4 / 256, 256>>>(x);
    k_norms<<<NN / 8, 256>>>(x);
    k_ce<<<NN / 128, 128>>>(sc, tg);
    k_dist<<<ITILES * JHALVES, THREADS, SM_TOTAL>>>(tg);
    k_merge<<<NN / 256, 256>>>();
    k_final<<<1, 1>>>(out);
}

// round 9
// speedup vs baseline: 2.0444x; 1.2414x over previous
#include <cuda_runtime.h>
#include <cuda_bf16.h>
#include <float.h>
#include <math.h>
#include <stdint.h>

#define NN 8192
#define DD 128
#define CC 7
#define KNN 5
#define EPSF 1e-6f

#define BM 128
#define BN 64
#define THREADS 512
#define JQUARTERS 4
#define JTILES (NN / JQUARTERS / BN)   // 32 j-tiles per CTA
#define ITILES (NN / BM)               // 64 i-tiles

#define ASTRIDE 272                    // 128 bf16 = 256B + 16B pad

// ---------------- smem map (bytes) ----------------
#define SM_CT   0                       // float2 [2][64]  (cn, tg-bits)
#define SM_A    1024                    // 128 * 272 = 34816
#define SM_B    35840                   // 2 stages * 17408
#define SM_BSTG 17408
#define SM_TOTAL 70656
// merge overlay reuses B region: 128 rows * 8 slots * 5 floats = 20480 B

// ---------------- device scratch ----------------
__device__ __nv_bfloat16 g_hi[NN * DD];
__device__ float  g_rn[NN];
__device__ float  g_cn[NN];
__device__ float  g_part5[JQUARTERS][NN][KNN];
__device__ double g_accCE;
__device__ double g_accPair;

// ---------------- PTX helpers ----------------
__device__ __forceinline__ uint32_t smem_u32(const void* p) {
    uint32_t a;
    asm("{ .reg .u64 t; cvta.to.shared.u64 t, %1; cvt.u32.u64 %0, t; }" : "=r"(a) : "l"(p));
    return a;
}
__device__ __forceinline__ void cp16(uint32_t s, const void* g) {
    asm volatile("cp.async.cg.shared.global [%0], [%1], 16;" :: "r"(s), "l"(g));
}
#define CP_COMMIT() asm volatile("cp.async.commit_group;" ::: "memory")
#define CP_WAIT1()  asm volatile("cp.async.wait_group 1;" ::: "memory")

__device__ __forceinline__ void ldsm4(uint32_t* r, uint32_t a) {
    asm volatile("ldmatrix.sync.aligned.m8n8.x4.shared.b16 {%0,%1,%2,%3}, [%4];"
                 : "=r"(r[0]), "=r"(r[1]), "=r"(r[2]), "=r"(r[3]) : "r"(a));
}
__device__ __forceinline__ void mma_bf16(float* c, const uint32_t* a, const uint32_t* b) {
    asm volatile("mma.sync.aligned.m16n8k16.row.col.f32.bf16.bf16.f32 "
                 "{%0,%1,%2,%3}, {%4,%5,%6,%7}, {%8,%9}, {%0,%1,%2,%3};"
                 : "+f"(c[0]), "+f"(c[1]), "+f"(c[2]), "+f"(c[3])
                 : "r"(a[0]), "r"(a[1]), "r"(a[2]), "r"(a[3]), "r"(b[0]), "r"(b[1]));
}

#define T5_INSERT(arr, thv, val)                                              \
    do {                                                                      \
        int _mi = 0; float _mv = (arr)[0];                                    \
        _Pragma("unroll")                                                     \
        for (int _k = 1; _k < KNN; _k++)                                      \
            if ((arr)[_k] > _mv) { _mv = (arr)[_k]; _mi = _k; }               \
        _Pragma("unroll")                                                     \
        for (int _k = 0; _k < KNN; _k++) if (_k == _mi) (arr)[_k] = (val);    \
        (thv) = (arr)[0];                                                     \
        _Pragma("unroll")                                                     \
        for (int _k = 1; _k < KNN; _k++) (thv) = fmaxf((thv), (arr)[_k]);     \
    } while (0)

// ---------------- small kernels ----------------
__global__ void k_init() { g_accCE = 0.0; g_accPair = 0.0; }

__global__ void k_convert(const float* __restrict__ x) {
    int idx = blockIdx.x * blockDim.x + threadIdx.x;     // NN*DD/4 threads
    float4 v = reinterpret_cast<const float4*>(x)[idx];
    __nv_bfloat162 hh0 = {__float2bfloat16(v.x), __float2bfloat16(v.y)};
    __nv_bfloat162 hh1 = {__float2bfloat16(v.z), __float2bfloat16(v.w)};
    reinterpret_cast<__nv_bfloat162*>(g_hi)[idx * 2]     = hh0;
    reinterpret_cast<__nv_bfloat162*>(g_hi)[idx * 2 + 1] = hh1;
}

__global__ void k_norms(const float* __restrict__ x) {
    int row  = blockIdx.x * 8 + (threadIdx.x >> 5);
    int lane = threadIdx.x & 31;
    float4 v = reinterpret_cast<const float4*>(x + (size_t)row * DD)[lane];
    float s  = v.x + v.y + v.z + v.w;
    float n2 = v.x * v.x + v.y * v.y + v.z * v.z + v.w * v.w;
#pragma unroll
    for (int o = 16; o > 0; o >>= 1) {
        s  += __shfl_xor_sync(0xffffffffu, s, o);
        n2 += __shfl_xor_sync(0xffffffffu, n2, o);
    }
    if (lane == 0) {
        g_rn[row] = n2 + 2.0f * EPSF * s + (float)DD * EPSF * EPSF;
        g_cn[row] = n2 - 2.0f * EPSF * s;
    }
}

__global__ void k_ce(const float* __restrict__ sc, const int* __restrict__ tg) {
    int i = blockIdx.x * blockDim.x + threadIdx.x;
    const float* s = sc + (size_t)i * CC;
    float m = s[0];
#pragma unroll
    for (int c = 1; c < CC; c++) m = fmaxf(m, s[c]);
    float sum = 0.f;
#pragma unroll
    for (int c = 0; c < CC; c++) sum += expf(s[c] - m);
    float ce = m + logf(sum) - s[tg[i]];

    __shared__ double sh[128];
    sh[threadIdx.x] = (double)ce;
    __syncthreads();
#pragma unroll
    for (int o = 64; o > 0; o >>= 1) {
        if (threadIdx.x < o) sh[threadIdx.x] += sh[threadIdx.x + o];
        __syncthreads();
    }
    if (threadIdx.x == 0) atomicAdd(&g_accCE, sh[0]);
}

// ---------------- fused bf16 mma.sync GEMM + register top-5 (2 CTA/SM) ----------------
__global__ void __launch_bounds__(THREADS, 2)
k_dist(const int* __restrict__ tgt) {
    extern __shared__ char smem[];
    uint32_t smb = smem_u32(smem);
    int tid  = threadIdx.x;
    int lane = tid & 31;
    int w    = tid >> 5;
    int wm   = w >> 1;          // 0..7 : 16-row block
    int wn   = w & 1;           // 0..1 : 32-col block

    int it      = blockIdx.x >> 2;
    int jq      = blockIdx.x & 3;
    int rowBase = it * BM;
    int jBase0  = jq * (NN / JQUARTERS);

    float2* sCT = (float2*)(smem + SM_CT);   // [2][64] : {cn, tg-bits}

    // ---- prologue: A (2048 chunks, 4/thread) ----
#pragma unroll
    for (int itc = 0; itc < 4; itc++) {
        int q   = itc * THREADS + tid;
        int row = q >> 4;
        int c   = q & 15;
        cp16(smb + SM_A + row * ASTRIDE + c * 16,
             g_hi + (size_t)(rowBase + row) * DD + c * 8);
    }
    // ---- B tile 0 (1024 chunks, 2/thread) ----
#pragma unroll
    for (int itc = 0; itc < 2; itc++) {
        int q   = itc * THREADS + tid;
        int row = q >> 4;
        int c   = q & 15;
        cp16(smb + SM_B + row * ASTRIDE + c * 16,
             g_hi + (size_t)(jBase0 + row) * DD + c * 8);
    }
    CP_COMMIT();
    if (tid < BN)
        sCT[tid] = make_float2(g_cn[jBase0 + tid], __int_as_float(tgt[jBase0 + tid]));

    // ---- per-thread row state: 2 rows ----
    int   lrow[2];
    float rnq[2];
    int   tgq[2];
#pragma unroll
    for (int q = 0; q < 2; q++) {
        lrow[q] = wm * 16 + (lane >> 2) + (q << 3);
        rnq[q]  = g_rn[rowBase + lrow[q]];
        tgq[q]  = tgt[rowBase + lrow[q]];
    }
    float t5[2][KNN];
    float th[2];
#pragma unroll
    for (int q = 0; q < 2; q++) {
        th[q] = FLT_MAX;
#pragma unroll
        for (int k = 0; k < KNN; k++) t5[q][k] = FLT_MAX;
    }

    // ldmatrix base addresses (same fragment layouts as verified R8 kernel)
    uint32_t aOff  = smb + SM_A + (wm * 16 + (lane & 15)) * ASTRIDE + (lane >> 4) * 16;
    uint32_t bRow4 = (wn * 32 + ((lane >> 4) << 3) + (lane & 7)) * ASTRIDE + (((lane >> 3) & 1) << 4);

    for (int u = 0; u < JTILES; u++) {
        __syncthreads();              // epilogue(u-1) done: stage reusable
        if (u + 1 < JTILES) {
            int jb = jBase0 + (u + 1) * BN;
            uint32_t bs = smb + SM_B + ((u + 1) & 1) * SM_BSTG;
#pragma unroll
            for (int itc = 0; itc < 2; itc++) {
                int q   = itc * THREADS + tid;
                int row = q >> 4;
                int c   = q & 15;
                cp16(bs + row * ASTRIDE + c * 16,
                     g_hi + (size_t)(jb + row) * DD + c * 8);
            }
            if (tid < BN) {
                int slot = (u + 1) & 1;
                sCT[slot * BN + tid] =
                    make_float2(g_cn[jb + tid], __int_as_float(tgt[jb + tid]));
            }
        }
        CP_COMMIT();
        CP_WAIT1();                   // B(u) (and A) resident
        __syncthreads();

        // ---- preload cn/tg columns (4x LDS.128) ----
        float4 ct[4];
        {
            int slot = (u & 1) * BN;
#pragma unroll
            for (int ni = 0; ni < 4; ni++) {
                int cb = wn * 32 + ni * 8 + 2 * (lane & 3);
                ct[ni] = *reinterpret_cast<const float4*>(&sCT[slot + cb]);
            }
        }

        // ---- MMA: acc = A*B^T over K=128 ----
        float acc[4][4];
#pragma unroll
        for (int ni = 0; ni < 4; ni++)
#pragma unroll
            for (int q = 0; q < 4; q++) acc[ni][q] = 0.f;

        uint32_t bH = smb + SM_B + (u & 1) * SM_BSTG + bRow4;

#pragma unroll
        for (int kk = 0; kk < 8; kk++) {
            uint32_t ah[4], bh[4][2];
            ldsm4(ah, aOff + kk * 32);
#pragma unroll
            for (int pr = 0; pr < 2; pr++)
                ldsm4(&bh[pr * 2][0], bH + pr * 16 * ASTRIDE + kk * 32);
#pragma unroll
            for (int ni = 0; ni < 4; ni++)
                mma_bf16(acc[ni], ah, bh[ni]);
        }

        // ---- register epilogue ----
        {
            int jb = jBase0 + u * BN;
            int sj[2];
#pragma unroll
            for (int q = 0; q < 2; q++) sj[q] = (rowBase + lrow[q]) - jb;

#pragma unroll
            for (int ni = 0; ni < 4; ni++) {
                int cb = wn * 32 + ni * 8 + 2 * (lane & 3);
                float cn0 = ct[ni].x, cn1 = ct[ni].z;
                int   tg0 = __float_as_int(ct[ni].y), tg1 = __float_as_int(ct[ni].w);
#pragma unroll
                for (int q = 0; q < 2; q++) {
                    float d2a = fmaf(-2.0f, acc[ni][2 * q],     rnq[q] + cn0);
                    float d2b = fmaf(-2.0f, acc[ni][2 * q + 1], rnq[q] + cn1);
                    if (d2a < th[q] && tg0 == tgq[q] && cb != sj[q])
                        T5_INSERT(t5[q], th[q], d2a);
                    if (d2b < th[q] && tg1 == tgq[q] && (cb + 1) != sj[q])
                        T5_INSERT(t5[q], th[q], d2b);
                }
            }
        }
    }

    // ---- in-CTA merge: 8 partials per row ----
    __syncthreads();
    float* M = (float*)(smem + SM_B);      // overlay, 20480 B
    int slot8 = wn * 4 + (lane & 3);
#pragma unroll
    for (int q = 0; q < 2; q++)
#pragma unroll
        for (int k = 0; k < KNN; k++)
            M[(lrow[q] * 8 + slot8) * KNN + k] = t5[q][k];
    __syncthreads();

    if (tid < BM) {
        const float* mrow = M + tid * 8 * KNN;
        float best[KNN], bth = FLT_MAX;
#pragma unroll
        for (int k = 0; k < KNN; k++) best[k] = FLT_MAX;
#pragma unroll
        for (int j = 0; j < 8 * KNN; j++) {
            float v = mrow[j];
            if (v < bth) T5_INSERT(best, bth, v);
        }
#pragma unroll
        for (int k = 0; k < KNN; k++) g_part5[jq][rowBase + tid][k] = best[k];
    }
}

// ---------------- merge + pair sum ----------------
__global__ void k_merge() {
    int i = blockIdx.x * blockDim.x + threadIdx.x;
    float v[JQUARTERS * KNN];
#pragma unroll
    for (int sp = 0; sp < JQUARTERS; sp++)
#pragma unroll
        for (int k = 0; k < KNN; k++) v[sp * KNN + k] = g_part5[sp][i][k];

    float sum = 0.f;
#pragma unroll
    for (int sel = 0; sel < KNN; sel++) {
        float mv = v[0]; int mi = 0;
#pragma unroll
        for (int k = 1; k < JQUARTERS * KNN; k++)
            if (v[k] < mv) { mv = v[k]; mi = k; }
        if (mv < 1e37f) sum += mv;
#pragma unroll
        for (int k = 0; k < JQUARTERS * KNN; k++)
            if (k == mi) v[k] = FLT_MAX;
    }

    __shared__ double sh[256];
    sh[threadIdx.x] = (double)sum / (double)DD;
    __syncthreads();
#pragma unroll
    for (int o = 128; o > 0; o >>= 1) {
        if (threadIdx.x < o) sh[threadIdx.x] += sh[threadIdx.x + o];
        __syncthreads();
    }
    if (threadIdx.x == 0) atomicAdd(&g_accPair, sh[0]);
}

__global__ void k_final(float* out) {
    out[0] = (float)(g_accCE / (double)NN + (0.5 / (double)KNN) * g_accPair);
}

// ---------------- launch ----------------
extern "C" void kernel_launch(void* const* d_in, const int* in_sizes, int n_in,
                              void* d_out, int out_size) {
    const float* x  = nullptr;
    const float* sc = nullptr;
    const int*   tg = nullptr;
    for (int i = 0; i < n_in; i++) {
        if (in_sizes[i] == NN * DD)      x  = (const float*)d_in[i];
        else if (in_sizes[i] == NN * CC) sc = (const float*)d_in[i];
        else if (in_sizes[i] == NN)      tg = (const int*)d_in[i];
    }
    float* out = (float*)d_out;

    cudaFuncSetAttribute(k_dist, cudaFuncAttributeMaxDynamicSharedMemorySize, SM_TOTAL);

    k_init<<<1, 1>>>();
    k_convert<<<NN * DD / 4 / 256, 256>>>(x);
    k_norms<<<NN / 8, 256>>>(x);
    k_ce<<<NN / 128, 128>>>(sc, tg);
    k_dist<<<ITILES * JQUARTERS, THREADS, SM_TOTAL>>>(tg);
    k_merge<<<NN / 256, 256>>>();
    k_final<<<1, 1>>>(out);
}

// round 10
// speedup vs baseline: 2.0674x; 1.0113x over previous
#include <cuda_runtime.h>
#include <cuda_bf16.h>
#include <float.h>
#include <math.h>
#include <stdint.h>

#define NN 8192
#define DD 128
#define CC 7
#define KNN 5
#define EPSF 1e-6f

#define BM 64
#define BN 64
#define THREADS 256
#define JQUARTERS 4
#define JTILES (NN / JQUARTERS / BN)   // 32 j-tiles per CTA
#define ITILES (NN / BM)               // 128 i-tiles

#define ASTRIDE 272                    // 128 bf16 = 256B + 16B pad

// ---------------- smem map (bytes) ----------------
#define SM_CT   0                       // float2 [2][64]  (cn, tg-bits)
#define SM_A    1024                    // 64 * 272 = 17408
#define SM_B    18432                   // 2 stages * 17408
#define SM_BSTG 17408
#define SM_TOTAL 53248
// merge overlay reuses B region: 64 rows * 8 slots * 5 floats = 10240 B

// ---------------- device scratch ----------------
__device__ __nv_bfloat16 g_hi[NN * DD];
__device__ float  g_rn[NN];
__device__ float  g_cn[NN];
__device__ float  g_part5[JQUARTERS][NN][KNN];
__device__ double g_accCE;
__device__ double g_accPair;

// ---------------- PTX helpers ----------------
__device__ __forceinline__ uint32_t smem_u32(const void* p) {
    uint32_t a;
    asm("{ .reg .u64 t; cvta.to.shared.u64 t, %1; cvt.u32.u64 %0, t; }" : "=r"(a) : "l"(p));
    return a;
}
__device__ __forceinline__ void cp16(uint32_t s, const void* g) {
    asm volatile("cp.async.cg.shared.global [%0], [%1], 16;" :: "r"(s), "l"(g));
}
#define CP_COMMIT() asm volatile("cp.async.commit_group;" ::: "memory")
#define CP_WAIT1()  asm volatile("cp.async.wait_group 1;" ::: "memory")

__device__ __forceinline__ void ldsm4(uint32_t* r, uint32_t a) {
    asm volatile("ldmatrix.sync.aligned.m8n8.x4.shared.b16 {%0,%1,%2,%3}, [%4];"
                 : "=r"(r[0]), "=r"(r[1]), "=r"(r[2]), "=r"(r[3]) : "r"(a));
}
__device__ __forceinline__ void mma_bf16(float* c, const uint32_t* a, const uint32_t* b) {
    asm volatile("mma.sync.aligned.m16n8k16.row.col.f32.bf16.bf16.f32 "
                 "{%0,%1,%2,%3}, {%4,%5,%6,%7}, {%8,%9}, {%0,%1,%2,%3};"
                 : "+f"(c[0]), "+f"(c[1]), "+f"(c[2]), "+f"(c[3])
                 : "r"(a[0]), "r"(a[1]), "r"(a[2]), "r"(a[3]), "r"(b[0]), "r"(b[1]));
}

#define T5_INSERT(arr, thv, val)                                              \
    do {                                                                      \
        int _mi = 0; float _mv = (arr)[0];                                    \
        _Pragma("unroll")                                                     \
        for (int _k = 1; _k < KNN; _k++)                                      \
            if ((arr)[_k] > _mv) { _mv = (arr)[_k]; _mi = _k; }               \
        _Pragma("unroll")                                                     \
        for (int _k = 0; _k < KNN; _k++) if (_k == _mi) (arr)[_k] = (val);    \
        (thv) = (arr)[0];                                                     \
        _Pragma("unroll")                                                     \
        for (int _k = 1; _k < KNN; _k++) (thv) = fmaxf((thv), (arr)[_k]);     \
    } while (0)

// ---------------- small kernels ----------------
__global__ void k_init() { g_accCE = 0.0; g_accPair = 0.0; }

__global__ void k_convert(const float* __restrict__ x) {
    int idx = blockIdx.x * blockDim.x + threadIdx.x;     // NN*DD/4 threads
    float4 v = reinterpret_cast<const float4*>(x)[idx];
    __nv_bfloat162 hh0 = {__float2bfloat16(v.x), __float2bfloat16(v.y)};
    __nv_bfloat162 hh1 = {__float2bfloat16(v.z), __float2bfloat16(v.w)};
    reinterpret_cast<__nv_bfloat162*>(g_hi)[idx * 2]     = hh0;
    reinterpret_cast<__nv_bfloat162*>(g_hi)[idx * 2 + 1] = hh1;
}

__global__ void k_norms(const float* __restrict__ x) {
    int row  = blockIdx.x * 8 + (threadIdx.x >> 5);
    int lane = threadIdx.x & 31;
    float4 v = reinterpret_cast<const float4*>(x + (size_t)row * DD)[lane];
    float s  = v.x + v.y + v.z + v.w;
    float n2 = v.x * v.x + v.y * v.y + v.z * v.z + v.w * v.w;
#pragma unroll
    for (int o = 16; o > 0; o >>= 1) {
        s  += __shfl_xor_sync(0xffffffffu, s, o);
        n2 += __shfl_xor_sync(0xffffffffu, n2, o);
    }
    if (lane == 0) {
        g_rn[row] = n2 + 2.0f * EPSF * s + (float)DD * EPSF * EPSF;
        g_cn[row] = n2 - 2.0f * EPSF * s;
    }
}

__global__ void k_ce(const float* __restrict__ sc, const int* __restrict__ tg) {
    int i = blockIdx.x * blockDim.x + threadIdx.x;
    const float* s = sc + (size_t)i * CC;
    float m = s[0];
#pragma unroll
    for (int c = 1; c < CC; c++) m = fmaxf(m, s[c]);
    float sum = 0.f;
#pragma unroll
    for (int c = 0; c < CC; c++) sum += expf(s[c] - m);
    float ce = m + logf(sum) - s[tg[i]];

    __shared__ double sh[128];
    sh[threadIdx.x] = (double)ce;
    __syncthreads();
#pragma unroll
    for (int o = 64; o > 0; o >>= 1) {
        if (threadIdx.x < o) sh[threadIdx.x] += sh[threadIdx.x + o];
        __syncthreads();
    }
    if (threadIdx.x == 0) atomicAdd(&g_accCE, sh[0]);
}

// ---------------- fused bf16 mma.sync GEMM + register top-5 (4 CTA/SM) ----------------
__global__ void __launch_bounds__(THREADS, 4)
k_dist(const int* __restrict__ tgt) {
    extern __shared__ char smem[];
    uint32_t smb = smem_u32(smem);
    int tid  = threadIdx.x;
    int lane = tid & 31;
    int w    = tid >> 5;
    int wm   = w >> 1;          // 0..3 : 16-row block
    int wn   = w & 1;           // 0..1 : 32-col block

    int it      = blockIdx.x >> 2;
    int jq      = blockIdx.x & 3;
    int rowBase = it * BM;
    int jBase0  = jq * (NN / JQUARTERS);

    float2* sCT = (float2*)(smem + SM_CT);   // [2][64] : {cn, tg-bits}

    // ---- prologue: A (1024 chunks, 4/thread) ----
#pragma unroll
    for (int itc = 0; itc < 4; itc++) {
        int q   = itc * THREADS + tid;
        int row = q >> 4;
        int c   = q & 15;
        cp16(smb + SM_A + row * ASTRIDE + c * 16,
             g_hi + (size_t)(rowBase + row) * DD + c * 8);
    }
    // ---- B tile 0 (1024 chunks, 4/thread) ----
#pragma unroll
    for (int itc = 0; itc < 4; itc++) {
        int q   = itc * THREADS + tid;
        int row = q >> 4;
        int c   = q & 15;
        cp16(smb + SM_B + row * ASTRIDE + c * 16,
             g_hi + (size_t)(jBase0 + row) * DD + c * 8);
    }
    CP_COMMIT();
    if (tid < BN)
        sCT[tid] = make_float2(g_cn[jBase0 + tid], __int_as_float(tgt[jBase0 + tid]));

    // ---- per-thread row state: 2 rows ----
    int   lrow[2];
    float rnq[2];
    int   tgq[2];
#pragma unroll
    for (int q = 0; q < 2; q++) {
        lrow[q] = wm * 16 + (lane >> 2) + (q << 3);
        rnq[q]  = g_rn[rowBase + lrow[q]];
        tgq[q]  = tgt[rowBase + lrow[q]];
    }
    float t5[2][KNN];
    float th[2];
#pragma unroll
    for (int q = 0; q < 2; q++) {
        th[q] = FLT_MAX;
#pragma unroll
        for (int k = 0; k < KNN; k++) t5[q][k] = FLT_MAX;
    }

    // ldmatrix base addresses (fragment layouts identical to verified R9)
    uint32_t aOff  = smb + SM_A + (wm * 16 + (lane & 15)) * ASTRIDE + (lane >> 4) * 16;
    uint32_t bRow4 = (wn * 32 + ((lane >> 4) << 3) + (lane & 7)) * ASTRIDE + (((lane >> 3) & 1) << 4);

    for (int u = 0; u < JTILES; u++) {
        __syncthreads();              // epilogue(u-1) done: stage reusable
        if (u + 1 < JTILES) {
            int jb = jBase0 + (u + 1) * BN;
            uint32_t bs = smb + SM_B + ((u + 1) & 1) * SM_BSTG;
#pragma unroll
            for (int itc = 0; itc < 4; itc++) {
                int q   = itc * THREADS + tid;
                int row = q >> 4;
                int c   = q & 15;
                cp16(bs + row * ASTRIDE + c * 16,
                     g_hi + (size_t)(jb + row) * DD + c * 8);
            }
            if (tid < BN) {
                int slot = (u + 1) & 1;
                sCT[slot * BN + tid] =
                    make_float2(g_cn[jb + tid], __int_as_float(tgt[jb + tid]));
            }
        }
        CP_COMMIT();
        CP_WAIT1();                   // B(u) (and A) resident
        __syncthreads();

        // ---- preload cn/tg columns (4x LDS.128) ----
        float4 ct[4];
        {
            int slot = (u & 1) * BN;
#pragma unroll
            for (int ni = 0; ni < 4; ni++) {
                int cb = wn * 32 + ni * 8 + 2 * (lane & 3);
                ct[ni] = *reinterpret_cast<const float4*>(&sCT[slot + cb]);
            }
        }

        // ---- MMA: acc = A*B^T over K=128 ----
        float acc[4][4];
#pragma unroll
        for (int ni = 0; ni < 4; ni++)
#pragma unroll
            for (int q = 0; q < 4; q++) acc[ni][q] = 0.f;

        uint32_t bH = smb + SM_B + (u & 1) * SM_BSTG + bRow4;

#pragma unroll
        for (int kk = 0; kk < 8; kk++) {
            uint32_t ah[4], bh[4][2];
            ldsm4(ah, aOff + kk * 32);
#pragma unroll
            for (int pr = 0; pr < 2; pr++)
                ldsm4(&bh[pr * 2][0], bH + pr * 16 * ASTRIDE + kk * 32);
#pragma unroll
            for (int ni = 0; ni < 4; ni++)
                mma_bf16(acc[ni], ah, bh[ni]);
        }

        // ---- register epilogue ----
        {
            int jb = jBase0 + u * BN;
            int sj[2];
#pragma unroll
            for (int q = 0; q < 2; q++) sj[q] = (rowBase + lrow[q]) - jb;

#pragma unroll
            for (int ni = 0; ni < 4; ni++) {
                int cb = wn * 32 + ni * 8 + 2 * (lane & 3);
                float cn0 = ct[ni].x, cn1 = ct[ni].z;
                int   tg0 = __float_as_int(ct[ni].y), tg1 = __float_as_int(ct[ni].w);
#pragma unroll
                for (int q = 0; q < 2; q++) {
                    float d2a = fmaf(-2.0f, acc[ni][2 * q],     rnq[q] + cn0);
                    float d2b = fmaf(-2.0f, acc[ni][2 * q + 1], rnq[q] + cn1);
                    if (d2a < th[q] && tg0 == tgq[q] && cb != sj[q])
                        T5_INSERT(t5[q], th[q], d2a);
                    if (d2b < th[q] && tg1 == tgq[q] && (cb + 1) != sj[q])
                        T5_INSERT(t5[q], th[q], d2b);
                }
            }
        }
    }

    // ---- in-CTA merge: 8 partials per row ----
    __syncthreads();
    float* M = (float*)(smem + SM_B);      // overlay, 10240 B
    int slot8 = wn * 4 + (lane & 3);
#pragma unroll
    for (int q = 0; q < 2; q++)
#pragma unroll
        for (int k = 0; k < KNN; k++)
            M[(lrow[q] * 8 + slot8) * KNN + k] = t5[q][k];
    __syncthreads();

    if (tid < BM) {
        const float* mrow = M + tid * 8 * KNN;
        float best[KNN], bth = FLT_MAX;
#pragma unroll
        for (int k = 0; k < KNN; k++) best[k] = FLT_MAX;
#pragma unroll
        for (int j = 0; j < 8 * KNN; j++) {
            float v = mrow[j];
            if (v < bth) T5_INSERT(best, bth, v);
        }
#pragma unroll
        for (int k = 0; k < KNN; k++) g_part5[jq][rowBase + tid][k] = best[k];
    }
}

// ---------------- merge + pair sum ----------------
__global__ void k_merge() {
    int i = blockIdx.x * blockDim.x + threadIdx.x;
    float v[JQUARTERS * KNN];
#pragma unroll
    for (int sp = 0; sp < JQUARTERS; sp++)
#pragma unroll
        for (int k = 0; k < KNN; k++) v[sp * KNN + k] = g_part5[sp][i][k];

    float sum = 0.f;
#pragma unroll
    for (int sel = 0; sel < KNN; sel++) {
        float mv = v[0]; int mi = 0;
#pragma unroll
        for (int k = 1; k < JQUARTERS * KNN; k++)
            if (v[k] < mv) { mv = v[k]; mi = k; }
        if (mv < 1e37f) sum += mv;
#pragma unroll
        for (int k = 0; k < JQUARTERS * KNN; k++)
            if (k == mi) v[k] = FLT_MAX;
    }

    __shared__ double sh[256];
    sh[threadIdx.x] = (double)sum / (double)DD;
    __syncthreads();
#pragma unroll
    for (int o = 128; o > 0; o >>= 1) {
        if (threadIdx.x < o) sh[threadIdx.x] += sh[threadIdx.x + o];
        __syncthreads();
    }
    if (threadIdx.x == 0) atomicAdd(&g_accPair, sh[0]);
}

__global__ void k_final(float* out) {
    out[0] = (float)(g_accCE / (double)NN + (0.5 / (double)KNN) * g_accPair);
}

// ---------------- launch ----------------
extern "C" void kernel_launch(void* const* d_in, const int* in_sizes, int n_in,
                              void* d_out, int out_size) {
    const float* x  = nullptr;
    const float* sc = nullptr;
    const int*   tg = nullptr;
    for (int i = 0; i < n_in; i++) {
        if (in_sizes[i] == NN * DD)      x  = (const float*)d_in[i];
        else if (in_sizes[i] == NN * CC) sc = (const float*)d_in[i];
        else if (in_sizes[i] == NN)      tg = (const int*)d_in[i];
    }
    float* out = (float*)d_out;

    cudaFuncSetAttribute(k_dist, cudaFuncAttributeMaxDynamicSharedMemorySize, SM_TOTAL);

    k_init<<<1, 1>>>();
    k_convert<<<NN * DD / 4 / 256, 256>>>(x);
    k_norms<<<NN / 8, 256>>>(x);
    k_ce<<<NN / 128, 128>>>(sc, tg);
    k_dist<<<ITILES * JQUARTERS, THREADS, SM_TOTAL>>>(tg);
    k_merge<<<NN / 256, 256>>>();
    k_final<<<1, 1>>>(out);
}

// round 12
// speedup vs baseline: 2.0681x; 1.0004x over previous
#include <cuda_runtime.h>
#include <cuda_bf16.h>
#include <float.h>
#include <math.h>
#include <stdint.h>

#define NN 8192
#define DD 128
#define CC 7
#define KNN 5
#define EPSF 1e-6f

#define BM 64
#define BN 64
#define THREADS 256
#define JQUARTERS 4
#define JTILES (NN / JQUARTERS / BN)   // 32 j-tiles per CTA
#define ITILES (NN / BM)               // 128 i-tiles

#define ASTRIDE 272                    // 128 bf16 = 256B + 16B pad

// ---------------- smem map (bytes) ----------------
#define SM_CT   0                       // float2 [2][64]  (cn, tg-bits)
#define SM_A    1024                    // 64 * 272 = 17408
#define SM_B    18432                   // 2 stages * 17408
#define SM_BSTG 17408
#define SM_TOTAL 53248
// merge overlay reuses B region: 64 rows * 8 slots * 5 floats = 10240 B

// ---------------- device scratch ----------------
__device__ __nv_bfloat16 g_hi[NN * DD];
__device__ float  g_rn[NN];
__device__ float  g_cn[NN];
__device__ float  g_part5[JQUARTERS][NN][KNN];
__device__ double g_accCE;
__device__ double g_accPair;

// ---------------- PTX helpers ----------------
__device__ __forceinline__ uint32_t smem_u32(const void* p) {
    uint32_t a;
    asm("{ .reg .u64 t; cvta.to.shared.u64 t, %1; cvt.u32.u64 %0, t; }" : "=r"(a) : "l"(p));
    return a;
}
__device__ __forceinline__ void cp16(uint32_t s, const void* g) {
    asm volatile("cp.async.cg.shared.global [%0], [%1], 16;" :: "r"(s), "l"(g));
}
#define CP_COMMIT() asm volatile("cp.async.commit_group;" ::: "memory")
#define CP_WAIT0()  asm volatile("cp.async.wait_group 0;" ::: "memory")

__device__ __forceinline__ void ldsm4(uint32_t* r, uint32_t a) {
    asm volatile("ldmatrix.sync.aligned.m8n8.x4.shared.b16 {%0,%1,%2,%3}, [%4];"
                 : "=r"(r[0]), "=r"(r[1]), "=r"(r[2]), "=r"(r[3]) : "r"(a));
}
__device__ __forceinline__ void mma_bf16(float* c, const uint32_t* a, const uint32_t* b) {
    asm volatile("mma.sync.aligned.m16n8k16.row.col.f32.bf16.bf16.f32 "
                 "{%0,%1,%2,%3}, {%4,%5,%6,%7}, {%8,%9}, {%0,%1,%2,%3};"
                 : "+f"(c[0]), "+f"(c[1]), "+f"(c[2]), "+f"(c[3])
                 : "r"(a[0]), "r"(a[1]), "r"(a[2]), "r"(a[3]), "r"(b[0]), "r"(b[1]));
}

#define T5_INSERT(arr, thv, val)                                              \
    do {                                                                      \
        int _mi = 0; float _mv = (arr)[0];                                    \
        _Pragma("unroll")                                                     \
        for (int _k = 1; _k < KNN; _k++)                                      \
            if ((arr)[_k] > _mv) { _mv = (arr)[_k]; _mi = _k; }               \
        _Pragma("unroll")                                                     \
        for (int _k = 0; _k < KNN; _k++) if (_k == _mi) (arr)[_k] = (val);    \
        (thv) = (arr)[0];                                                     \
        _Pragma("unroll")                                                     \
        for (int _k = 1; _k < KNN; _k++) (thv) = fmaxf((thv), (arr)[_k]);     \
    } while (0)

// ---------------- small kernels ----------------
__global__ void k_init() { g_accCE = 0.0; g_accPair = 0.0; }

__global__ void k_convert(const float* __restrict__ x) {
    int idx = blockIdx.x * blockDim.x + threadIdx.x;     // NN*DD/4 threads
    float4 v = reinterpret_cast<const float4*>(x)[idx];
    __nv_bfloat162 hh0 = {__float2bfloat16(v.x), __float2bfloat16(v.y)};
    __nv_bfloat162 hh1 = {__float2bfloat16(v.z), __float2bfloat16(v.w)};
    reinterpret_cast<__nv_bfloat162*>(g_hi)[idx * 2]     = hh0;
    reinterpret_cast<__nv_bfloat162*>(g_hi)[idx * 2 + 1] = hh1;
}

__global__ void k_norms(const float* __restrict__ x) {
    int row  = blockIdx.x * 8 + (threadIdx.x >> 5);
    int lane = threadIdx.x & 31;
    float4 v = reinterpret_cast<const float4*>(x + (size_t)row * DD)[lane];
    float s  = v.x + v.y + v.z + v.w;
    float n2 = v.x * v.x + v.y * v.y + v.z * v.z + v.w * v.w;
#pragma unroll
    for (int o = 16; o > 0; o >>= 1) {
        s  += __shfl_xor_sync(0xffffffffu, s, o);
        n2 += __shfl_xor_sync(0xffffffffu, n2, o);
    }
    if (lane == 0) {
        g_rn[row] = n2 + 2.0f * EPSF * s + (float)DD * EPSF * EPSF;
        g_cn[row] = n2 - 2.0f * EPSF * s;
    }
}

__global__ void k_ce(const float* __restrict__ sc, const int* __restrict__ tg) {
    int i = blockIdx.x * blockDim.x + threadIdx.x;
    const float* s = sc + (size_t)i * CC;
    float m = s[0];
#pragma unroll
    for (int c = 1; c < CC; c++) m = fmaxf(m, s[c]);
    float sum = 0.f;
#pragma unroll
    for (int c = 0; c < CC; c++) sum += expf(s[c] - m);
    float ce = m + logf(sum) - s[tg[i]];

    __shared__ double sh[128];
    sh[threadIdx.x] = (double)ce;
    __syncthreads();
#pragma unroll
    for (int o = 64; o > 0; o >>= 1) {
        if (threadIdx.x < o) sh[threadIdx.x] += sh[threadIdx.x + o];
        __syncthreads();
    }
    if (threadIdx.x == 0) atomicAdd(&g_accCE, sh[0]);
}

// ---------------- fused bf16 mma.sync GEMM + register top-5 (4 CTA/SM, 1 sync/tile) ----------------
__global__ void __launch_bounds__(THREADS, 4)
k_dist(const int* __restrict__ tgt) {
    extern __shared__ char smem[];
    uint32_t smb = smem_u32(smem);
    int tid  = threadIdx.x;
    int lane = tid & 31;
    int w    = tid >> 5;
    int wm   = w >> 1;          // 0..3 : 16-row block
    int wn   = w & 1;           // 0..1 : 32-col block

    int it      = blockIdx.x >> 2;
    int jq      = blockIdx.x & 3;
    int rowBase = it * BM;
    int jBase0  = jq * (NN / JQUARTERS);

    float2* sCT = (float2*)(smem + SM_CT);   // [2][64] : {cn, tg-bits}

    // ---- prologue: A + B(0) in one group ----
#pragma unroll
    for (int itc = 0; itc < 4; itc++) {
        int q   = itc * THREADS + tid;
        int row = q >> 4;
        int c   = q & 15;
        cp16(smb + SM_A + row * ASTRIDE + c * 16,
             g_hi + (size_t)(rowBase + row) * DD + c * 8);
    }
#pragma unroll
    for (int itc = 0; itc < 4; itc++) {
        int q   = itc * THREADS + tid;
        int row = q >> 4;
        int c   = q & 15;
        cp16(smb + SM_B + row * ASTRIDE + c * 16,
             g_hi + (size_t)(jBase0 + row) * DD + c * 8);
    }
    CP_COMMIT();
    if (tid < BN)
        sCT[tid] = make_float2(g_cn[jBase0 + tid], __int_as_float(tgt[jBase0 + tid]));

    // ---- per-thread row state: 2 rows ----
    int   lrow[2];
    float rnq[2];
    int   tgq[2];
#pragma unroll
    for (int q = 0; q < 2; q++) {
        lrow[q] = wm * 16 + (lane >> 2) + (q << 3);
        rnq[q]  = g_rn[rowBase + lrow[q]];
        tgq[q]  = tgt[rowBase + lrow[q]];
    }
    float t5[2][KNN];
    float th[2];
#pragma unroll
    for (int q = 0; q < 2; q++) {
        th[q] = FLT_MAX;
#pragma unroll
        for (int k = 0; k < KNN; k++) t5[q][k] = FLT_MAX;
    }

    // ldmatrix base addresses (fragment layouts identical to verified R10)
    uint32_t aOff  = smb + SM_A + (wm * 16 + (lane & 15)) * ASTRIDE + (lane >> 4) * 16;
    uint32_t bRow4 = (wn * 32 + ((lane >> 4) << 3) + (lane & 7)) * ASTRIDE + (((lane >> 3) & 1) << 4);

    for (int u = 0; u < JTILES; u++) {
        // pre-issue next-slot cn/tg loads (hide LDG latency under barrier)
        float2 nct;
        bool   haveN = (u + 1 < JTILES) && (tid < BN);
        if (haveN) {
            int jb = jBase0 + (u + 1) * BN;
            nct = make_float2(g_cn[jb + tid], __int_as_float(tgt[jb + tid]));
        }

        CP_WAIT0();                   // own B(u) (and A at u=0) done
        __syncthreads();              // all threads' B(u) landed; all warps done MMA(u-1)

        // prefetch B(u+1) into stage (u+1)&1 (safe: MMA(u-1) complete everywhere)
        if (u + 1 < JTILES) {
            int jb = jBase0 + (u + 1) * BN;
            uint32_t bs = smb + SM_B + ((u + 1) & 1) * SM_BSTG;
#pragma unroll
            for (int itc = 0; itc < 4; itc++) {
                int q   = itc * THREADS + tid;
                int row = q >> 4;
                int c   = q & 15;
                cp16(bs + row * ASTRIDE + c * 16,
                     g_hi + (size_t)(jb + row) * DD + c * 8);
            }
            if (haveN) sCT[((u + 1) & 1) * BN + tid] = nct;
        }
        CP_COMMIT();

        // ---- preload cn/tg columns (4x LDS.128) ----
        float4 ct[4];
        {
            int slot = (u & 1) * BN;
#pragma unroll
            for (int ni = 0; ni < 4; ni++) {
                int cb = wn * 32 + ni * 8 + 2 * (lane & 3);
                ct[ni] = *reinterpret_cast<const float4*>(&sCT[slot + cb]);
            }
        }

        // ---- MMA: acc = A*B^T over K=128 ----
        float acc[4][4];
#pragma unroll
        for (int ni = 0; ni < 4; ni++)
#pragma unroll
            for (int q = 0; q < 4; q++) acc[ni][q] = 0.f;

        uint32_t bH = smb + SM_B + (u & 1) * SM_BSTG + bRow4;

#pragma unroll
        for (int kk = 0; kk < 8; kk++) {
            uint32_t ah[4], bh[4][2];
            ldsm4(ah, aOff + kk * 32);
#pragma unroll
            for (int pr = 0; pr < 2; pr++)
                ldsm4(&bh[pr * 2][0], bH + pr * 16 * ASTRIDE + kk * 32);
#pragma unroll
            for (int ni = 0; ni < 4; ni++)
                mma_bf16(acc[ni], ah, bh[ni]);
        }

        // ---- register epilogue ----
        {
            int jb = jBase0 + u * BN;
            int sj[2];
#pragma unroll
            for (int q = 0; q < 2; q++) sj[q] = (rowBase + lrow[q]) - jb;

#pragma unroll
            for (int ni = 0; ni < 4; ni++) {
                int cb = wn * 32 + ni * 8 + 2 * (lane & 3);
                float cn0 = ct[ni].x, cn1 = ct[ni].z;
                int   tg0 = __float_as_int(ct[ni].y), tg1 = __float_as_int(ct[ni].w);
#pragma unroll
                for (int q = 0; q < 2; q++) {
                    float d2a = fmaf(-2.0f, acc[ni][2 * q],     rnq[q] + cn0);
                    float d2b = fmaf(-2.0f, acc[ni][2 * q + 1], rnq[q] + cn1);
                    if (d2a < th[q] && tg0 == tgq[q] && cb != sj[q])
                        T5_INSERT(t5[q], th[q], d2a);
                    if (d2b < th[q] && tg1 == tgq[q] && (cb + 1) != sj[q])
                        T5_INSERT(t5[q], th[q], d2b);
                }
            }
        }
    }

    // ---- in-CTA merge: 8 partials per row ----
    __syncthreads();
    float* M = (float*)(smem + SM_B);      // overlay, 10240 B
    int slot8 = wn * 4 + (lane & 3);
#pragma unroll
    for (int q = 0; q < 2; q++)
#pragma unroll
        for (int k = 0; k < KNN; k++)
            M[(lrow[q] * 8 + slot8) * KNN + k] = t5[q][k];
    __syncthreads();

    if (tid < BM) {
        const float* mrow = M + tid * 8 * KNN;
        float best[KNN], bth = FLT_MAX;
#pragma unroll
        for (int k = 0; k < KNN; k++) best[k] = FLT_MAX;
#pragma unroll
        for (int j = 0; j < 8 * KNN; j++) {
            float v = mrow[j];
            if (v < bth) T5_INSERT(best, bth, v);
        }
#pragma unroll
        for (int k = 0; k < KNN; k++) g_part5[jq][rowBase + tid][k] = best[k];
    }
}

// ---------------- merge + pair sum ----------------
__global__ void k_merge() {
    int i = blockIdx.x * blockDim.x + threadIdx.x;
    float v[JQUARTERS * KNN];
#pragma unroll
    for (int sp = 0; sp < JQUARTERS; sp++)
#pragma unroll
        for (int k = 0; k < KNN; k++) v[sp * KNN + k] = g_part5[sp][i][k];

    float sum = 0.f;
#pragma unroll
    for (int sel = 0; sel < KNN; sel++) {
        float mv = v[0]; int mi = 0;
#pragma unroll
        for (int k = 1; k < JQUARTERS * KNN; k++)
            if (v[k] < mv) { mv = v[k]; mi = k; }
        if (mv < 1e37f) sum += mv;
#pragma unroll
        for (int k = 0; k < JQUARTERS * KNN; k++)
            if (k == mi) v[k] = FLT_MAX;
    }

    __shared__ double sh[256];
    sh[threadIdx.x] = (double)sum / (double)DD;
    __syncthreads();
#pragma unroll
    for (int o = 128; o > 0; o >>= 1) {
        if (threadIdx.x < o) sh[threadIdx.x] += sh[threadIdx.x + o];
        __syncthreads();
    }
    if (threadIdx.x == 0) atomicAdd(&g_accPair, sh[0]);
}

__global__ void k_final(float* out) {
    out[0] = (float)(g_accCE / (double)NN + (0.5 / (double)KNN) * g_accPair);
}

// ---------------- launch ----------------
extern "C" void kernel_launch(void* const* d_in, const int* in_sizes, int n_in,
                              void* d_out, int out_size) {
    const float* x  = nullptr;
    const float* sc = nullptr;
    const int*   tg = nullptr;
    for (int i = 0; i < n_in; i++) {
        if (in_sizes[i] == NN * DD)      x  = (const float*)d_in[i];
        else if (in_sizes[i] == NN * CC) sc = (const float*)d_in[i];
        else if (in_sizes[i] == NN)      tg = (const int*)d_in[i];
    }
    float* out = (float*)d_out;

    cudaFuncSetAttribute(k_dist, cudaFuncAttributeMaxDynamicSharedMemorySize, SM_TOTAL);

    k_init<<<1, 1>>>();
    k_convert<<<NN * DD / 4 / 256, 256>>>(x);
    k_norms<<<NN / 8, 256>>>(x);
    k_ce<<<NN / 128, 128>>>(sc, tg);
    k_dist<<<ITILES * JQUARTERS, THREADS, SM_TOTAL>>>(tg);
    k_merge<<<NN / 256, 256>>>();
    k_final<<<1, 1>>>(out);
}